// round 7
// baseline (speedup 1.0000x reference)
#include <cuda_runtime.h>
#include <cuda_bf16.h>
#include <math.h>
#include <stdint.h>

#define NG 8
#define LN 1024
#define NH 8
#define HD 16
#define DS 64
#define NNODE (NG*LN)
#define NEDGE 131072
#define BH (NG*NH)
#define MSZ (1024ULL*1024ULL)

typedef __nv_bfloat16 bf16;
typedef __nv_bfloat162 bf162;

// ---------------- scratch (__device__ globals, allocation-free) ----------------
__device__ float g_T[BH*MSZ];
__device__ float g_G[NG*MSZ];
__device__ float g_s0[NH*NNODE], g_s1[NH*NNODE];
__device__ float g_denom[BH*LN], g_dtself[BH*LN];
__device__ bf16 g_Lh[BH*MSZ], g_Ll[BH*MSZ];
__device__ bf16 g_Sh[BH*MSZ], g_Sl[BH*MSZ];
__device__ bf16 g_Oh[BH*MSZ], g_Ol[BH*MSZ];
__device__ bf16 g_Ph[BH*MSZ], g_Pl[BH*MSZ];

// ---------------- PTX helpers (plain-sm_103-legal) ----------------
__device__ __forceinline__ uint32_t smem_u32(const void* p) {
    uint32_t a;
    asm("{ .reg .u64 t; cvta.to.shared.u64 t, %1; cvt.u32.u64 %0, t; }" : "=r"(a) : "l"(p));
    return a;
}
__device__ __forceinline__ void cp16(uint32_t dst, const void* src) {
    asm volatile("cp.async.cg.shared.global [%0], [%1], 16;" :: "r"(dst), "l"(src));
}
__device__ __forceinline__ void ldsm4(uint32_t& r0, uint32_t& r1, uint32_t& r2, uint32_t& r3,
                                      uint32_t addr) {
    asm volatile("ldmatrix.sync.aligned.m8n8.x4.shared.b16 {%0,%1,%2,%3}, [%4];"
                 : "=r"(r0), "=r"(r1), "=r"(r2), "=r"(r3) : "r"(addr));
}
__device__ __forceinline__ void ldsm4t(uint32_t& r0, uint32_t& r1, uint32_t& r2, uint32_t& r3,
                                       uint32_t addr) {
    asm volatile("ldmatrix.sync.aligned.m8n8.x4.trans.shared.b16 {%0,%1,%2,%3}, [%4];"
                 : "=r"(r0), "=r"(r1), "=r"(r2), "=r"(r3) : "r"(addr));
}
__device__ __forceinline__ void mma16816(float* c, const uint32_t* a, const uint32_t* b) {
    asm volatile(
        "mma.sync.aligned.m16n8k16.row.col.f32.bf16.bf16.f32 "
        "{%0,%1,%2,%3}, {%4,%5,%6,%7}, {%8,%9}, {%0,%1,%2,%3};"
        : "+f"(c[0]), "+f"(c[1]), "+f"(c[2]), "+f"(c[3])
        : "r"(a[0]), "r"(a[1]), "r"(a[2]), "r"(a[3]), "r"(b[0]), "r"(b[1]));
}

// ---------------- prep ----------------
__device__ __forceinline__ float softplus_f(float z) {
    return (z > 20.f) ? z : log1pf(expf(z));
}

__global__ void coef_kernel(const float* __restrict__ dt, const float* __restrict__ dt_bias) {
    int n = blockIdx.x * 256 + threadIdx.x;
    if (n >= NNODE) return;
    int b = n >> 10, l = n & 1023;
    #pragma unroll
    for (int h = 0; h < NH; h++) {
        float bias = dt_bias[h];
        const float* p = dt + (size_t)n * (NH * 4) + h * 4;
        float a0 = -softplus_f(p[0] + bias);
        float a1 = -softplus_f(p[1] + bias);
        float a2 = -softplus_f(p[2] + bias);
        g_s0[h * NNODE + n] = expf(0.5f * a0);
        g_s1[h * NNODE + n] = expf(0.5f * a1);
        g_denom[(b * NH + h) * LN + l] = expf(a2) + 0.1f;
        g_dtself[(b * NH + h) * LN + l] = p[3];
    }
}

__global__ void zero_kernel(float4* __restrict__ p) {
    size_t i = (size_t)blockIdx.x * 256 + threadIdx.x;
    p[i] = make_float4(0.f, 0.f, 0.f, 0.f);
}

__global__ void scatter_kernel(const int* __restrict__ src, const int* __restrict__ dst) {
    int e = blockIdx.x * 128 + threadIdx.x;
    if (e >= NEDGE) return;
    int s = src[e], d = dst[e];
    int b = s >> 10, sl = s & 1023, dl = d & 1023;
    #pragma unroll
    for (int h = 0; h < NH; h++) {
        float attr = g_s0[h * NNODE + s] * g_s1[h * NNODE + d];
        size_t base = ((size_t)(b * NH + h) * LN + dl) * LN + sl;  // transposed layout
        atomicAdd(&g_T[base], attr);
        atomicAdd(&g_denom[(b * NH + h) * LN + sl], attr);
    }
}

// M[bh,i,j] = g_T[bh,i,j] / denom[bh,j];  L = M (hi/lo);  O = I + M (hi/lo)
__global__ void build_kernel() {
    size_t idx = (size_t)blockIdx.x * 256 + threadIdx.x;
    int j = (int)(idx & 1023);
    size_t r = idx >> 10;
    int bh = (int)(r >> 10);
    int i  = (int)(r & 1023);
    float v = g_T[idx] / g_denom[bh * LN + j];
    bf16 h = __float2bfloat16(v);
    g_Lh[idx] = h;
    g_Ll[idx] = __float2bfloat16(v - __bfloat162float(h));
    float vo = v + ((i == j) ? 1.f : 0.f);
    bf16 ho = __float2bfloat16(vo);
    g_Oh[idx] = ho;
    g_Ol[idx] = __float2bfloat16(vo - __bfloat162float(ho));
}

// ---------------- bf16-split HMMA GEMM ----------------
// C = A@B (+O), batched over z. Block 128x256, 8 warps (2m x 4n), warp tile 64x64.
// K-stage 32, 3-stage cp.async pipeline, 1 CTA/SM.
#define STAGES 3
#define A_STAGE 16384          // 128 rows x 128B (hi 64B + lo 64B per row)
#define B_STAGE 32768          // 32 rows x 1024B (hi 512B + lo 512B per row)
#define STAGE_BYTES (A_STAGE + B_STAGE)
#define SMEM_REQ (STAGES * STAGE_BYTES)

template<bool ADD_O>
__global__ void __launch_bounds__(256, 1)
hgemm_kernel(const bf16* __restrict__ Ah, const bf16* __restrict__ Al,
             const bf16* __restrict__ Bh, const bf16* __restrict__ Bl,
             bf16* __restrict__ Ch, bf16* __restrict__ Cl,
             const bf16* __restrict__ Oh, const bf16* __restrict__ Ol)
{
    extern __shared__ char smraw[];
    const uint32_t sbase = smem_u32(smraw);

    const int tid = threadIdx.x;
    const int lane = tid & 31;
    const int warp = tid >> 5;
    const int wm0 = (warp & 1) * 64;
    const int wn0 = (warp >> 1) * 64;
    const int m0 = blockIdx.y * 128;
    const int n0 = blockIdx.x * 256;
    const size_t zoff = (size_t)blockIdx.z * MSZ;
    Ah += zoff; Al += zoff; Bh += zoff; Bl += zoff; Ch += zoff; Cl += zoff;
    if (ADD_O) { Oh += zoff; Ol += zoff; }

    auto load_stage = [&](int ks) {
        int s = ks % STAGES;
        int k0 = ks << 5;
        uint32_t sa = sbase + s * STAGE_BYTES;
        uint32_t sb = sa + A_STAGE;
        #pragma unroll
        for (int i = 0; i < 4; i++) {
            int idx = tid + (i << 8);
            int r = idx >> 3, c = idx & 7;
            uint32_t dst = sa + r * 128 + ((c ^ (r & 7)) << 4);
            const bf16* src = ((c & 4) ? Al : Ah) + (size_t)(m0 + r) * 1024 + k0 + ((c & 3) << 3);
            cp16(dst, src);
        }
        #pragma unroll
        for (int i = 0; i < 8; i++) {
            int idx = tid + (i << 8);
            int r = idx >> 6, c = idx & 63;
            uint32_t dst = sb + r * 1024 + ((c ^ (r & 7)) << 4);
            const bf16* src = ((c & 32) ? Bl : Bh) + (size_t)(k0 + r) * 1024 + n0 + ((c & 31) << 3);
            cp16(dst, src);
        }
    };

    float acc[4][8][4];
    #pragma unroll
    for (int i = 0; i < 4; i++)
        #pragma unroll
        for (int j = 0; j < 8; j++)
            #pragma unroll
            for (int q = 0; q < 4; q++) acc[i][j][q] = 0.f;

    load_stage(0);
    asm volatile("cp.async.commit_group;" ::: "memory");
    load_stage(1);
    asm volatile("cp.async.commit_group;" ::: "memory");

    for (int ks = 0; ks < 32; ks++) {
        asm volatile("cp.async.wait_group 1;" ::: "memory");
        __syncthreads();
        int s = ks % STAGES;
        uint32_t sa = sbase + s * STAGE_BYTES;
        uint32_t sb = sa + A_STAGE;

        #pragma unroll
        for (int st = 0; st < 2; st++) {
            uint32_t aH[4][4], aL[4][4], bP[8][2];
            // A hi + lo planes (rows wm0..wm0+63, k-halves by st)
            #pragma unroll
            for (int t = 0; t < 4; t++) {
                int row = wm0 + t * 16 + (lane & 15);
                int ch = (st << 1) + (lane >> 4);              // hi plane
                uint32_t addr = sa + row * 128 + ((ch ^ (row & 7)) << 4);
                ldsm4(aH[t][0], aH[t][1], aH[t][2], aH[t][3], addr);
            }
            #pragma unroll
            for (int t = 0; t < 4; t++) {
                int row = wm0 + t * 16 + (lane & 15);
                int ch = 4 + (st << 1) + (lane >> 4);          // lo plane
                uint32_t addr = sa + row * 128 + ((ch ^ (row & 7)) << 4);
                ldsm4(aL[t][0], aL[t][1], aL[t][2], aL[t][3], addr);
            }
            // B hi plane
            #pragma unroll
            for (int pr = 0; pr < 4; pr++) {
                int g = lane >> 3, j2 = lane & 7;
                int row = st * 16 + ((g & 1) << 3) + j2;
                int ch = (wn0 >> 3) + (pr << 1) + (g >> 1);    // hi plane
                uint32_t addr = sb + row * 1024 + ((ch ^ (row & 7)) << 4);
                ldsm4t(bP[2*pr][0], bP[2*pr][1], bP[2*pr+1][0], bP[2*pr+1][1], addr);
            }
            #pragma unroll
            for (int i = 0; i < 4; i++)
                #pragma unroll
                for (int j = 0; j < 8; j++)
                    mma16816(acc[i][j], aH[i], bP[j]);         // hi*hi
            #pragma unroll
            for (int i = 0; i < 4; i++)
                #pragma unroll
                for (int j = 0; j < 8; j++)
                    mma16816(acc[i][j], aL[i], bP[j]);         // lo*hi
            // B lo plane (overwrite bP)
            #pragma unroll
            for (int pr = 0; pr < 4; pr++) {
                int g = lane >> 3, j2 = lane & 7;
                int row = st * 16 + ((g & 1) << 3) + j2;
                int ch = 32 + (wn0 >> 3) + (pr << 1) + (g >> 1);
                uint32_t addr = sb + row * 1024 + ((ch ^ (row & 7)) << 4);
                ldsm4t(bP[2*pr][0], bP[2*pr][1], bP[2*pr+1][0], bP[2*pr+1][1], addr);
            }
            #pragma unroll
            for (int i = 0; i < 4; i++)
                #pragma unroll
                for (int j = 0; j < 8; j++)
                    mma16816(acc[i][j], aH[i], bP[j]);         // hi*lo
        }

        if (ks + 2 < 32) load_stage(ks + 2);
        asm volatile("cp.async.commit_group;" ::: "memory");
    }

    // epilogue: split fp32 acc to bf16 hi/lo, optional +O
    #pragma unroll
    for (int i = 0; i < 4; i++) {
        #pragma unroll
        for (int j = 0; j < 8; j++) {
            int row = m0 + wm0 + i * 16 + (lane >> 2);
            int col = n0 + wn0 + j * 8 + ((lane & 3) << 1);
            #pragma unroll
            for (int half = 0; half < 2; half++) {
                int rr = row + half * 8;
                float v0 = acc[i][j][half * 2 + 0];
                float v1 = acc[i][j][half * 2 + 1];
                size_t gi = (size_t)rr * 1024 + col;
                if (ADD_O) {
                    bf162 oh = *(const bf162*)(Oh + gi);
                    bf162 ol = *(const bf162*)(Ol + gi);
                    v0 += __bfloat162float(oh.x) + __bfloat162float(ol.x);
                    v1 += __bfloat162float(oh.y) + __bfloat162float(ol.y);
                }
                bf16 h0 = __float2bfloat16(v0);
                bf16 l0 = __float2bfloat16(v0 - __bfloat162float(h0));
                bf16 h1 = __float2bfloat16(v1);
                bf16 l1 = __float2bfloat16(v1 - __bfloat162float(h1));
                bf162 hh; hh.x = h0; hh.y = h1;
                bf162 ll; ll.x = l0; ll.y = l1;
                *(bf162*)(Ch + gi) = hh;
                *(bf162*)(Cl + gi) = ll;
            }
        }
    }
}

// ---------------- Gram: G[b,l,t] = sum_d C[b,l,d]*B[b,t,d] ----------------
__global__ void gram_kernel(const float* __restrict__ Bm, const float* __restrict__ Cm) {
    int b = blockIdx.z;
    __shared__ float Cs[16][65];
    __shared__ float Bs[16][65];
    int tid = threadIdx.y * 16 + threadIdx.x;
    for (int i = tid; i < 16 * 64; i += 256) {
        int r = i >> 6, d = i & 63;
        Cs[r][d] = Cm[((size_t)b * LN + blockIdx.y * 16 + r) * DS + d];
        Bs[r][d] = Bm[((size_t)b * LN + blockIdx.x * 16 + r) * DS + d];
    }
    __syncthreads();
    float acc = 0.f;
    #pragma unroll
    for (int d = 0; d < DS; d++) acc += Cs[threadIdx.y][d] * Bs[threadIdx.x][d];
    int row = blockIdx.y * 16 + threadIdx.y;
    int col = blockIdx.x * 16 + threadIdx.x;
    g_G[((size_t)b * LN + row) * LN + col] = acc;
}

// ---------------- final ----------------
__global__ void final_kernel(const float* __restrict__ x, const float* __restrict__ D,
                             const bf16* __restrict__ Fh, const bf16* __restrict__ Fl,
                             float* __restrict__ out) {
    int l = blockIdx.x, h = blockIdx.y, b = blockIdx.z;
    int tid = threadIdx.x;
    size_t bh = (size_t)(b * NH + h);
    const bf16* Lh = Fh + ((bh << 10) + l) * 1024;
    const bf16* Ll = Fl + ((bh << 10) + l) * 1024;
    const float* ds = g_dtself + (bh << 10);
    const float* Grow = g_G + (((size_t)b << 10) + l) * 1024;

    float acc[HD];
    #pragma unroll
    for (int e = 0; e < HD; e++) acc[e] = 0.f;

    for (int t = tid; t < LN; t += 128) {
        float Lv = __bfloat162float(Lh[t]) + __bfloat162float(Ll[t]);
        float w = Lv * ds[t] * Grow[t];
        const float4* xp = (const float4*)(x + (((size_t)(b << 10) + t) << 7) + h * HD);
        #pragma unroll
        for (int q = 0; q < 4; q++) {
            float4 v = xp[q];
            acc[q*4+0] += w * v.x; acc[q*4+1] += w * v.y;
            acc[q*4+2] += w * v.z; acc[q*4+3] += w * v.w;
        }
    }
    #pragma unroll
    for (int e = 0; e < HD; e++) {
        #pragma unroll
        for (int o = 16; o > 0; o >>= 1)
            acc[e] += __shfl_down_sync(0xffffffffu, acc[e], o);
    }
    __shared__ float red[4][HD];
    int warp = tid >> 5, lane = tid & 31;
    if (lane == 0) {
        #pragma unroll
        for (int e = 0; e < HD; e++) red[warp][e] = acc[e];
    }
    __syncthreads();
    if (tid < HD) {
        float s = red[0][tid] + red[1][tid] + red[2][tid] + red[3][tid];
        size_t node = ((size_t)b << 10) + l;
        float xv = x[(node << 7) + h * HD + tid];
        out[(node << 7) + tid * NH + h] = s + D[h] * xv;
    }
}

// ---------------- launch ----------------
extern "C" void kernel_launch(void* const* d_in, const int* in_sizes, int n_in,
                              void* d_out, int out_size) {
    const float* x       = (const float*)d_in[0];
    const float* Bm      = (const float*)d_in[1];
    const float* Cm      = (const float*)d_in[2];
    const float* dt      = (const float*)d_in[3];
    const float* dt_bias = (const float*)d_in[4];
    const float* Dv      = (const float*)d_in[5];
    const int*   edges   = (const int*)d_in[6];
    float* out = (float*)d_out;

    float* pT;
    cudaGetSymbolAddress((void**)&pT, g_T);
    bf16 *Lh,*Ll,*Sh,*Sl,*Oh,*Ol,*Ph,*Pl;
    cudaGetSymbolAddress((void**)&Lh, g_Lh); cudaGetSymbolAddress((void**)&Ll, g_Ll);
    cudaGetSymbolAddress((void**)&Sh, g_Sh); cudaGetSymbolAddress((void**)&Sl, g_Sl);
    cudaGetSymbolAddress((void**)&Oh, g_Oh); cudaGetSymbolAddress((void**)&Ol, g_Ol);
    cudaGetSymbolAddress((void**)&Ph, g_Ph); cudaGetSymbolAddress((void**)&Pl, g_Pl);

    cudaFuncSetAttribute(hgemm_kernel<false>,
                         cudaFuncAttributeMaxDynamicSharedMemorySize, SMEM_REQ);
    cudaFuncSetAttribute(hgemm_kernel<true>,
                         cudaFuncAttributeMaxDynamicSharedMemorySize, SMEM_REQ);

    coef_kernel<<<(NNODE + 255) / 256, 256>>>(dt, dt_bias);
    zero_kernel<<<(int)(BH * MSZ / 4 / 256), 256>>>((float4*)pT);
    scatter_kernel<<<NEDGE / 128, 128>>>(edges, edges + NEDGE);
    build_kernel<<<(int)(BH * MSZ / 256), 256>>>();

    dim3 gg(4, 8, BH);
    for (int it = 0; it < 5; it++) {
        // S = L @ L
        hgemm_kernel<false><<<gg, 256, SMEM_REQ>>>(Lh, Ll, Lh, Ll, Sh, Sl, Lh, Ll);
        // P = O @ S + O
        hgemm_kernel<true><<<gg, 256, SMEM_REQ>>>(Oh, Ol, Sh, Sl, Ph, Pl, Oh, Ol);
        bf16* t;
        t = Lh; Lh = Sh; Sh = t;  t = Ll; Ll = Sl; Sl = t;
        t = Oh; Oh = Ph; Ph = t;  t = Ol; Ol = Pl; Pl = t;
    }

    gram_kernel<<<dim3(64, 64, NG), dim3(16, 16)>>>(Bm, Cm);
    final_kernel<<<dim3(LN, NH, NG), 128>>>(x, Dv, Oh, Ol, out);
}

// round 11
// speedup vs baseline: 1.0051x; 1.0051x over previous
#include <cuda_runtime.h>
#include <cuda_bf16.h>
#include <math.h>
#include <stdint.h>

#define NG 8
#define LN 1024
#define NH 8
#define HD 16
#define DS 64
#define NNODE (NG*LN)
#define NEDGE 131072
#define BH (NG*NH)
#define MSZ (1024ULL*1024ULL)

typedef __nv_bfloat16 bf16;
typedef __nv_bfloat162 bf162;

// ---------------- scratch (__device__ globals, allocation-free) ----------------
__device__ float g_T[BH*MSZ];
__device__ float g_G[NG*MSZ];
__device__ float g_s0[NH*NNODE], g_s1[NH*NNODE];
__device__ float g_denom[BH*LN], g_dtself[BH*LN];
__device__ bf16 g_Lh[BH*MSZ], g_Ll[BH*MSZ];
__device__ bf16 g_Sh[BH*MSZ], g_Sl[BH*MSZ];
__device__ bf16 g_Oh[BH*MSZ], g_Ol[BH*MSZ];
__device__ bf16 g_Ph[BH*MSZ], g_Pl[BH*MSZ];

// ---------------- PTX helpers (plain-sm_103-legal) ----------------
__device__ __forceinline__ uint32_t smem_u32(const void* p) {
    uint32_t a;
    asm("{ .reg .u64 t; cvta.to.shared.u64 t, %1; cvt.u32.u64 %0, t; }" : "=r"(a) : "l"(p));
    return a;
}
__device__ __forceinline__ void cp16(uint32_t dst, const void* src) {
    asm volatile("cp.async.cg.shared.global [%0], [%1], 16;" :: "r"(dst), "l"(src));
}
__device__ __forceinline__ void ldsm4(uint32_t& r0, uint32_t& r1, uint32_t& r2, uint32_t& r3,
                                      uint32_t addr) {
    asm volatile("ldmatrix.sync.aligned.m8n8.x4.shared.b16 {%0,%1,%2,%3}, [%4];"
                 : "=r"(r0), "=r"(r1), "=r"(r2), "=r"(r3) : "r"(addr));
}
__device__ __forceinline__ void ldsm4t(uint32_t& r0, uint32_t& r1, uint32_t& r2, uint32_t& r3,
                                       uint32_t addr) {
    asm volatile("ldmatrix.sync.aligned.m8n8.x4.trans.shared.b16 {%0,%1,%2,%3}, [%4];"
                 : "=r"(r0), "=r"(r1), "=r"(r2), "=r"(r3) : "r"(addr));
}
__device__ __forceinline__ void mma16816(float* c, const uint32_t* a, const uint32_t* b) {
    asm volatile(
        "mma.sync.aligned.m16n8k16.row.col.f32.bf16.bf16.f32 "
        "{%0,%1,%2,%3}, {%4,%5,%6,%7}, {%8,%9}, {%0,%1,%2,%3};"
        : "+f"(c[0]), "+f"(c[1]), "+f"(c[2]), "+f"(c[3])
        : "r"(a[0]), "r"(a[1]), "r"(a[2]), "r"(a[3]), "r"(b[0]), "r"(b[1]));
}

// ---------------- prep ----------------
__device__ __forceinline__ float softplus_f(float z) {
    return (z > 20.f) ? z : log1pf(expf(z));
}

__global__ void coef_kernel(const float* __restrict__ dt, const float* __restrict__ dt_bias) {
    int n = blockIdx.x * 256 + threadIdx.x;
    if (n >= NNODE) return;
    int b = n >> 10, l = n & 1023;
    #pragma unroll
    for (int h = 0; h < NH; h++) {
        float bias = dt_bias[h];
        const float* p = dt + (size_t)n * (NH * 4) + h * 4;
        float a0 = -softplus_f(p[0] + bias);
        float a1 = -softplus_f(p[1] + bias);
        float a2 = -softplus_f(p[2] + bias);
        g_s0[h * NNODE + n] = expf(0.5f * a0);
        g_s1[h * NNODE + n] = expf(0.5f * a1);
        g_denom[(b * NH + h) * LN + l] = expf(a2) + 0.1f;
        g_dtself[(b * NH + h) * LN + l] = p[3];
    }
}

__global__ void zero_kernel(float4* __restrict__ p) {
    size_t i = (size_t)blockIdx.x * 256 + threadIdx.x;
    p[i] = make_float4(0.f, 0.f, 0.f, 0.f);
}

__global__ void scatter_kernel(const int* __restrict__ src, const int* __restrict__ dst) {
    int e = blockIdx.x * 128 + threadIdx.x;
    if (e >= NEDGE) return;
    int s = src[e], d = dst[e];
    int b = s >> 10, sl = s & 1023, dl = d & 1023;
    #pragma unroll
    for (int h = 0; h < NH; h++) {
        float attr = g_s0[h * NNODE + s] * g_s1[h * NNODE + d];
        size_t base = ((size_t)(b * NH + h) * LN + dl) * LN + sl;  // transposed layout
        atomicAdd(&g_T[base], attr);
        atomicAdd(&g_denom[(b * NH + h) * LN + sl], attr);
    }
}

// M[bh,i,j] = g_T[bh,i,j] / denom[bh,j];  L = M (hi/lo);  O = I + M (hi/lo)
__global__ void build_kernel() {
    size_t idx = (size_t)blockIdx.x * 256 + threadIdx.x;
    int j = (int)(idx & 1023);
    size_t r = idx >> 10;
    int bh = (int)(r >> 10);
    int i  = (int)(r & 1023);
    float v = g_T[idx] / g_denom[bh * LN + j];
    bf16 h = __float2bfloat16(v);
    g_Lh[idx] = h;
    g_Ll[idx] = __float2bfloat16(v - __bfloat162float(h));
    float vo = v + ((i == j) ? 1.f : 0.f);
    bf16 ho = __float2bfloat16(vo);
    g_Oh[idx] = ho;
    g_Ol[idx] = __float2bfloat16(vo - __bfloat162float(ho));
}

// ---------------- bf16-split HMMA GEMM ----------------
// C = A@B (+O), batched over z. Block 128x128, 8 warps (2m x 4n), warp tile 64x32.
// K-stage 32, 3-stage cp.async pipeline, 2 CTAs/SM, prefetch-before-compute.
#define STAGES 3
#define A_STAGE 16384          // 128 rows x 128B (hi 64B + lo 64B per row)
#define B_STAGE 16384          // 32 rows x 512B (hi 256B + lo 256B per row)
#define STAGE_BYTES (A_STAGE + B_STAGE)
#define SMEM_REQ (STAGES * STAGE_BYTES)

template<bool ADD_O>
__global__ void __launch_bounds__(256, 2)
hgemm_kernel(const bf16* __restrict__ Ah, const bf16* __restrict__ Al,
             const bf16* __restrict__ Bh, const bf16* __restrict__ Bl,
             bf16* __restrict__ Ch, bf16* __restrict__ Cl,
             const bf16* __restrict__ Oh, const bf16* __restrict__ Ol)
{
    extern __shared__ char smraw[];
    const uint32_t sbase = smem_u32(smraw);

    const int tid = threadIdx.x;
    const int lane = tid & 31;
    const int warp = tid >> 5;
    const int wm0 = (warp & 1) * 64;
    const int wn0 = (warp >> 1) * 32;
    const int m0 = blockIdx.y * 128;
    const int n0 = blockIdx.x * 128;
    const size_t zoff = (size_t)blockIdx.z * MSZ;
    Ah += zoff; Al += zoff; Bh += zoff; Bl += zoff; Ch += zoff; Cl += zoff;
    if (ADD_O) { Oh += zoff; Ol += zoff; }

    auto load_stage = [&](int ks) {
        int s = ks % STAGES;
        int k0 = ks << 5;
        uint32_t sa = sbase + s * STAGE_BYTES;
        uint32_t sb = sa + A_STAGE;
        #pragma unroll
        for (int i = 0; i < 4; i++) {
            int idx = tid + (i << 8);
            int r = idx >> 3, c = idx & 7;
            uint32_t dst = sa + r * 128 + ((c ^ (r & 7)) << 4);
            const bf16* src = ((c & 4) ? Al : Ah) + (size_t)(m0 + r) * 1024 + k0 + ((c & 3) << 3);
            cp16(dst, src);
        }
        #pragma unroll
        for (int i = 0; i < 4; i++) {
            int idx = tid + (i << 8);
            int r = idx >> 5, c = idx & 31;
            uint32_t dst = sb + r * 512 + ((c ^ (r & 7)) << 4);
            const bf16* src = ((c & 16) ? Bl : Bh) + (size_t)(k0 + r) * 1024 + n0 + ((c & 15) << 3);
            cp16(dst, src);
        }
    };

    float acc[4][4][4];
    #pragma unroll
    for (int i = 0; i < 4; i++)
        #pragma unroll
        for (int j = 0; j < 4; j++)
            #pragma unroll
            for (int q = 0; q < 4; q++) acc[i][j][q] = 0.f;

    load_stage(0);
    asm volatile("cp.async.commit_group;" ::: "memory");
    load_stage(1);
    asm volatile("cp.async.commit_group;" ::: "memory");

    for (int ks = 0; ks < 32; ks++) {
        asm volatile("cp.async.wait_group 1;" ::: "memory");
        __syncthreads();
        int s = ks % STAGES;
        uint32_t sa = sbase + s * STAGE_BYTES;
        uint32_t sb = sa + A_STAGE;

        // prefetch next stage FIRST so memory stays busy during compute
        if (ks + 2 < 32) load_stage(ks + 2);
        asm volatile("cp.async.commit_group;" ::: "memory");

        #pragma unroll
        for (int st = 0; st < 2; st++) {
            uint32_t aH[4][4], aL[4][4], bH[4][2], bL[4][2];
            // hi planes
            #pragma unroll
            for (int t = 0; t < 4; t++) {
                int row = wm0 + t * 16 + (lane & 15);
                int ch = (st << 1) + (lane >> 4);           // plane 0
                uint32_t addr = sa + row * 128 + ((ch ^ (row & 7)) << 4);
                ldsm4(aH[t][0], aH[t][1], aH[t][2], aH[t][3], addr);
            }
            #pragma unroll
            for (int pr = 0; pr < 2; pr++) {
                int g = lane >> 3, j2 = lane & 7;
                int row = st * 16 + ((g & 1) << 3) + j2;
                int ch = (wn0 >> 3) + (pr << 1) + (g >> 1); // plane 0
                uint32_t addr = sb + row * 512 + ((ch ^ (row & 7)) << 4);
                ldsm4t(bH[2*pr][0], bH[2*pr][1], bH[2*pr+1][0], bH[2*pr+1][1], addr);
            }
            #pragma unroll
            for (int i = 0; i < 4; i++)
                #pragma unroll
                for (int j = 0; j < 4; j++)
                    mma16816(acc[i][j], aH[i], bH[j]);      // hi*hi
            // lo B plane
            #pragma unroll
            for (int pr = 0; pr < 2; pr++) {
                int g = lane >> 3, j2 = lane & 7;
                int row = st * 16 + ((g & 1) << 3) + j2;
                int ch = 16 + (wn0 >> 3) + (pr << 1) + (g >> 1);
                uint32_t addr = sb + row * 512 + ((ch ^ (row & 7)) << 4);
                ldsm4t(bL[2*pr][0], bL[2*pr][1], bL[2*pr+1][0], bL[2*pr+1][1], addr);
            }
            #pragma unroll
            for (int i = 0; i < 4; i++)
                #pragma unroll
                for (int j = 0; j < 4; j++)
                    mma16816(acc[i][j], aH[i], bL[j]);      // hi*lo
            // lo A plane
            #pragma unroll
            for (int t = 0; t < 4; t++) {
                int row = wm0 + t * 16 + (lane & 15);
                int ch = 4 + (st << 1) + (lane >> 4);
                uint32_t addr = sa + row * 128 + ((ch ^ (row & 7)) << 4);
                ldsm4(aL[t][0], aL[t][1], aL[t][2], aL[t][3], addr);
            }
            #pragma unroll
            for (int i = 0; i < 4; i++)
                #pragma unroll
                for (int j = 0; j < 4; j++)
                    mma16816(acc[i][j], aL[i], bH[j]);      // lo*hi
        }
    }

    // epilogue: split fp32 acc to bf16 hi/lo, optional +O
    #pragma unroll
    for (int i = 0; i < 4; i++) {
        #pragma unroll
        for (int j = 0; j < 4; j++) {
            int row = m0 + wm0 + i * 16 + (lane >> 2);
            int col = n0 + wn0 + j * 8 + ((lane & 3) << 1);
            #pragma unroll
            for (int half = 0; half < 2; half++) {
                int rr = row + half * 8;
                float v0 = acc[i][j][half * 2 + 0];
                float v1 = acc[i][j][half * 2 + 1];
                size_t gi = (size_t)rr * 1024 + col;
                if (ADD_O) {
                    bf162 oh = *(const bf162*)(Oh + gi);
                    bf162 ol = *(const bf162*)(Ol + gi);
                    v0 += __bfloat162float(oh.x) + __bfloat162float(ol.x);
                    v1 += __bfloat162float(oh.y) + __bfloat162float(ol.y);
                }
                bf16 h0 = __float2bfloat16(v0);
                bf16 l0 = __float2bfloat16(v0 - __bfloat162float(h0));
                bf16 h1 = __float2bfloat16(v1);
                bf16 l1 = __float2bfloat16(v1 - __bfloat162float(h1));
                bf162 hh; hh.x = h0; hh.y = h1;
                bf162 ll; ll.x = l0; ll.y = l1;
                *(bf162*)(Ch + gi) = hh;
                *(bf162*)(Cl + gi) = ll;
            }
        }
    }
}

// ---------------- Gram: G[b,l,t] = sum_d C[b,l,d]*B[b,t,d] ----------------
__global__ void gram_kernel(const float* __restrict__ Bm, const float* __restrict__ Cm) {
    int b = blockIdx.z;
    __shared__ float Cs[16][65];
    __shared__ float Bs[16][65];
    int tid = threadIdx.y * 16 + threadIdx.x;
    for (int i = tid; i < 16 * 64; i += 256) {
        int r = i >> 6, d = i & 63;
        Cs[r][d] = Cm[((size_t)b * LN + blockIdx.y * 16 + r) * DS + d];
        Bs[r][d] = Bm[((size_t)b * LN + blockIdx.x * 16 + r) * DS + d];
    }
    __syncthreads();
    float acc = 0.f;
    #pragma unroll
    for (int d = 0; d < DS; d++) acc += Cs[threadIdx.y][d] * Bs[threadIdx.x][d];
    int row = blockIdx.y * 16 + threadIdx.y;
    int col = blockIdx.x * 16 + threadIdx.x;
    g_G[((size_t)b * LN + row) * LN + col] = acc;
}

// ---------------- final ----------------
__global__ void final_kernel(const float* __restrict__ x, const float* __restrict__ D,
                             const bf16* __restrict__ Fh, const bf16* __restrict__ Fl,
                             float* __restrict__ out) {
    int l = blockIdx.x, h = blockIdx.y, b = blockIdx.z;
    int tid = threadIdx.x;
    size_t bh = (size_t)(b * NH + h);
    const bf16* Lh = Fh + ((bh << 10) + l) * 1024;
    const bf16* Ll = Fl + ((bh << 10) + l) * 1024;
    const float* ds = g_dtself + (bh << 10);
    const float* Grow = g_G + (((size_t)b << 10) + l) * 1024;

    float acc[HD];
    #pragma unroll
    for (int e = 0; e < HD; e++) acc[e] = 0.f;

    for (int t = tid; t < LN; t += 128) {
        float Lv = __bfloat162float(Lh[t]) + __bfloat162float(Ll[t]);
        float w = Lv * ds[t] * Grow[t];
        const float4* xp = (const float4*)(x + (((size_t)(b << 10) + t) << 7) + h * HD);
        #pragma unroll
        for (int q = 0; q < 4; q++) {
            float4 v = xp[q];
            acc[q*4+0] += w * v.x; acc[q*4+1] += w * v.y;
            acc[q*4+2] += w * v.z; acc[q*4+3] += w * v.w;
        }
    }
    #pragma unroll
    for (int e = 0; e < HD; e++) {
        #pragma unroll
        for (int o = 16; o > 0; o >>= 1)
            acc[e] += __shfl_down_sync(0xffffffffu, acc[e], o);
    }
    __shared__ float red[4][HD];
    int warp = tid >> 5, lane = tid & 31;
    if (lane == 0) {
        #pragma unroll
        for (int e = 0; e < HD; e++) red[warp][e] = acc[e];
    }
    __syncthreads();
    if (tid < HD) {
        float s = red[0][tid] + red[1][tid] + red[2][tid] + red[3][tid];
        size_t node = ((size_t)b << 10) + l;
        float xv = x[(node << 7) + h * HD + tid];
        out[(node << 7) + tid * NH + h] = s + D[h] * xv;
    }
}

// ---------------- launch ----------------
extern "C" void kernel_launch(void* const* d_in, const int* in_sizes, int n_in,
                              void* d_out, int out_size) {
    const float* x       = (const float*)d_in[0];
    const float* Bm      = (const float*)d_in[1];
    const float* Cm      = (const float*)d_in[2];
    const float* dt      = (const float*)d_in[3];
    const float* dt_bias = (const float*)d_in[4];
    const float* Dv      = (const float*)d_in[5];
    const int*   edges   = (const int*)d_in[6];
    float* out = (float*)d_out;

    float* pT;
    cudaGetSymbolAddress((void**)&pT, g_T);
    bf16 *Lh,*Ll,*Sh,*Sl,*Oh,*Ol,*Ph,*Pl;
    cudaGetSymbolAddress((void**)&Lh, g_Lh); cudaGetSymbolAddress((void**)&Ll, g_Ll);
    cudaGetSymbolAddress((void**)&Sh, g_Sh); cudaGetSymbolAddress((void**)&Sl, g_Sl);
    cudaGetSymbolAddress((void**)&Oh, g_Oh); cudaGetSymbolAddress((void**)&Ol, g_Ol);
    cudaGetSymbolAddress((void**)&Ph, g_Ph); cudaGetSymbolAddress((void**)&Pl, g_Pl);

    cudaFuncSetAttribute(hgemm_kernel<false>,
                         cudaFuncAttributeMaxDynamicSharedMemorySize, SMEM_REQ);
    cudaFuncSetAttribute(hgemm_kernel<true>,
                         cudaFuncAttributeMaxDynamicSharedMemorySize, SMEM_REQ);

    coef_kernel<<<(NNODE + 255) / 256, 256>>>(dt, dt_bias);
    zero_kernel<<<(int)(BH * MSZ / 4 / 256), 256>>>((float4*)pT);
    scatter_kernel<<<NEDGE / 128, 128>>>(edges, edges + NEDGE);
    build_kernel<<<(int)(BH * MSZ / 256), 256>>>();

    dim3 gg(8, 8, BH);
    for (int it = 0; it < 5; it++) {
        // S = L @ L
        hgemm_kernel<false><<<gg, 256, SMEM_REQ>>>(Lh, Ll, Lh, Ll, Sh, Sl, Lh, Ll);
        // P = O @ S + O
        hgemm_kernel<true><<<gg, 256, SMEM_REQ>>>(Oh, Ol, Sh, Sl, Ph, Pl, Oh, Ol);
        bf16* t;
        t = Lh; Lh = Sh; Sh = t;  t = Ll; Ll = Sl; Sl = t;
        t = Oh; Oh = Ph; Ph = t;  t = Ol; Ol = Pl; Pl = t;
    }

    gram_kernel<<<dim3(64, 64, NG), dim3(16, 16)>>>(Bm, Cm);
    final_kernel<<<dim3(LN, NH, NG), 128>>>(x, Dv, Oh, Ol, out);
}

// round 14
// speedup vs baseline: 1.0782x; 1.0728x over previous
#include <cuda_runtime.h>
#include <cuda_bf16.h>
#include <math.h>
#include <stdint.h>

#define NG 8
#define LN 1024
#define NH 8
#define HD 16
#define DS 64
#define NNODE (NG*LN)
#define NEDGE 131072
#define BH (NG*NH)
#define MSZ (1024ULL*1024ULL)

typedef __nv_bfloat16 bf16;
typedef __nv_bfloat162 bf162;

// ---------------- scratch (__device__ globals, allocation-free) ----------------
__device__ float g_T[BH*MSZ];
__device__ float g_G[NG*MSZ];
__device__ float g_s0[NH*NNODE], g_s1[NH*NNODE];
__device__ float g_denom[BH*LN], g_dtself[BH*LN];
__device__ bf16 g_Lh[BH*MSZ], g_Ll[BH*MSZ];
__device__ bf16 g_Sh[BH*MSZ], g_Sl[BH*MSZ];
__device__ bf16 g_Oh[BH*MSZ], g_Ol[BH*MSZ];
__device__ bf16 g_Ph[BH*MSZ], g_Pl[BH*MSZ];

// ---------------- PTX helpers (plain-sm_103-legal) ----------------
__device__ __forceinline__ uint32_t smem_u32(const void* p) {
    uint32_t a;
    asm("{ .reg .u64 t; cvta.to.shared.u64 t, %1; cvt.u32.u64 %0, t; }" : "=r"(a) : "l"(p));
    return a;
}
__device__ __forceinline__ void cp16(uint32_t dst, const void* src) {
    asm volatile("cp.async.cg.shared.global [%0], [%1], 16;" :: "r"(dst), "l"(src));
}
__device__ __forceinline__ void ldsm4(uint32_t& r0, uint32_t& r1, uint32_t& r2, uint32_t& r3,
                                      uint32_t addr) {
    asm volatile("ldmatrix.sync.aligned.m8n8.x4.shared.b16 {%0,%1,%2,%3}, [%4];"
                 : "=r"(r0), "=r"(r1), "=r"(r2), "=r"(r3) : "r"(addr));
}
__device__ __forceinline__ void ldsm4t(uint32_t& r0, uint32_t& r1, uint32_t& r2, uint32_t& r3,
                                       uint32_t addr) {
    asm volatile("ldmatrix.sync.aligned.m8n8.x4.trans.shared.b16 {%0,%1,%2,%3}, [%4];"
                 : "=r"(r0), "=r"(r1), "=r"(r2), "=r"(r3) : "r"(addr));
}
__device__ __forceinline__ void mma16816(float* c, const uint32_t* a, const uint32_t* b) {
    asm volatile(
        "mma.sync.aligned.m16n8k16.row.col.f32.bf16.bf16.f32 "
        "{%0,%1,%2,%3}, {%4,%5,%6,%7}, {%8,%9}, {%0,%1,%2,%3};"
        : "+f"(c[0]), "+f"(c[1]), "+f"(c[2]), "+f"(c[3])
        : "r"(a[0]), "r"(a[1]), "r"(a[2]), "r"(a[3]), "r"(b[0]), "r"(b[1]));
}

// ---------------- prep ----------------
__device__ __forceinline__ float softplus_f(float z) {
    return (z > 20.f) ? z : log1pf(expf(z));
}

__global__ void coef_kernel(const float* __restrict__ dt, const float* __restrict__ dt_bias) {
    int n = blockIdx.x * 256 + threadIdx.x;
    if (n >= NNODE) return;
    int b = n >> 10, l = n & 1023;
    #pragma unroll
    for (int h = 0; h < NH; h++) {
        float bias = dt_bias[h];
        const float* p = dt + (size_t)n * (NH * 4) + h * 4;
        float a0 = -softplus_f(p[0] + bias);
        float a1 = -softplus_f(p[1] + bias);
        float a2 = -softplus_f(p[2] + bias);
        g_s0[h * NNODE + n] = expf(0.5f * a0);
        g_s1[h * NNODE + n] = expf(0.5f * a1);
        g_denom[(b * NH + h) * LN + l] = expf(a2) + 0.1f;
        g_dtself[(b * NH + h) * LN + l] = p[3];
    }
}

__global__ void zero_kernel(float4* __restrict__ p) {
    size_t i = (size_t)blockIdx.x * 256 + threadIdx.x;
    p[i] = make_float4(0.f, 0.f, 0.f, 0.f);
}

__global__ void scatter_kernel(const int* __restrict__ src, const int* __restrict__ dst) {
    int e = blockIdx.x * 128 + threadIdx.x;
    if (e >= NEDGE) return;
    int s = src[e], d = dst[e];
    int b = s >> 10, sl = s & 1023, dl = d & 1023;
    #pragma unroll
    for (int h = 0; h < NH; h++) {
        float attr = g_s0[h * NNODE + s] * g_s1[h * NNODE + d];
        size_t base = ((size_t)(b * NH + h) * LN + dl) * LN + sl;  // transposed layout
        atomicAdd(&g_T[base], attr);
        atomicAdd(&g_denom[(b * NH + h) * LN + sl], attr);
    }
}

// M[bh,i,j] = g_T[bh,i,j] / denom[bh,j];  L = M (hi/lo);  O = I + M (hi/lo)
// Vectorized: 4 consecutive columns per thread.
__global__ void build_kernel() {
    size_t q = (size_t)blockIdx.x * 256 + threadIdx.x;   // 16M threads
    size_t idx = q << 2;
    int j0 = (int)(idx & 1023);
    size_t r = idx >> 10;
    int bh = (int)(r >> 10);
    int i  = (int)(r & 1023);
    float4 v4 = *(const float4*)(g_T + idx);
    float4 d4 = *(const float4*)(g_denom + bh * LN + j0);
    float v[4] = { v4.x / d4.x, v4.y / d4.y, v4.z / d4.z, v4.w / d4.w };
    bf16 lh[4], ll[4], oh[4], ol[4];
    #pragma unroll
    for (int q2 = 0; q2 < 4; q2++) {
        float x = v[q2];
        bf16 h = __float2bfloat16(x);
        lh[q2] = h;
        ll[q2] = __float2bfloat16(x - __bfloat162float(h));
        float xo = x + ((i == j0 + q2) ? 1.f : 0.f);
        bf16 ho = __float2bfloat16(xo);
        oh[q2] = ho;
        ol[q2] = __float2bfloat16(xo - __bfloat162float(ho));
    }
    *(uint2*)(g_Lh + idx) = *(uint2*)lh;
    *(uint2*)(g_Ll + idx) = *(uint2*)ll;
    *(uint2*)(g_Oh + idx) = *(uint2*)oh;
    *(uint2*)(g_Ol + idx) = *(uint2*)ol;
}

// ---------------- bf16-split HMMA GEMM (exact R6 winner) ----------------
// C = A@B (+O), batched over z. Block 128x128, 8 warps (2m x 4n), warp tile 64x32.
// K-stage 32, 3-stage cp.async pipeline, 2 CTAs/SM.
#define STAGES 3
#define A_STAGE 16384
#define B_STAGE 16384
#define STAGE_BYTES (A_STAGE + B_STAGE)
#define SMEM_REQ (STAGES * STAGE_BYTES)

template<bool ADD_O>
__global__ void __launch_bounds__(256, 2)
hgemm_kernel(const bf16* __restrict__ Ah, const bf16* __restrict__ Al,
             const bf16* __restrict__ Bh, const bf16* __restrict__ Bl,
             bf16* __restrict__ Ch, bf16* __restrict__ Cl,
             const bf16* __restrict__ Oh, const bf16* __restrict__ Ol)
{
    extern __shared__ char smraw[];
    const uint32_t sbase = smem_u32(smraw);

    const int tid = threadIdx.x;
    const int lane = tid & 31;
    const int warp = tid >> 5;
    const int wm0 = (warp & 1) * 64;
    const int wn0 = (warp >> 1) * 32;
    const int m0 = blockIdx.y * 128;
    const int n0 = blockIdx.x * 128;
    const size_t zoff = (size_t)blockIdx.z * MSZ;
    Ah += zoff; Al += zoff; Bh += zoff; Bl += zoff; Ch += zoff; Cl += zoff;
    if (ADD_O) { Oh += zoff; Ol += zoff; }

    auto load_stage = [&](int ks) {
        int s = ks % STAGES;
        int k0 = ks << 5;
        uint32_t sa = sbase + s * STAGE_BYTES;
        uint32_t sb = sa + A_STAGE;
        #pragma unroll
        for (int i = 0; i < 4; i++) {
            int idx = tid + (i << 8);
            int r = idx >> 3, c = idx & 7;
            uint32_t dst = sa + r * 128 + ((c ^ (r & 7)) << 4);
            const bf16* src = ((c & 4) ? Al : Ah) + (size_t)(m0 + r) * 1024 + k0 + ((c & 3) << 3);
            cp16(dst, src);
        }
        #pragma unroll
        for (int i = 0; i < 4; i++) {
            int idx = tid + (i << 8);
            int r = idx >> 5, c = idx & 31;
            uint32_t dst = sb + r * 512 + ((c ^ (r & 7)) << 4);
            const bf16* src = ((c & 16) ? Bl : Bh) + (size_t)(k0 + r) * 1024 + n0 + ((c & 15) << 3);
            cp16(dst, src);
        }
    };

    float acc[4][4][4];
    #pragma unroll
    for (int i = 0; i < 4; i++)
        #pragma unroll
        for (int j = 0; j < 4; j++)
            #pragma unroll
            for (int q = 0; q < 4; q++) acc[i][j][q] = 0.f;

    load_stage(0);
    asm volatile("cp.async.commit_group;" ::: "memory");
    load_stage(1);
    asm volatile("cp.async.commit_group;" ::: "memory");

    for (int ks = 0; ks < 32; ks++) {
        asm volatile("cp.async.wait_group 1;" ::: "memory");
        __syncthreads();
        int s = ks % STAGES;
        uint32_t sa = sbase + s * STAGE_BYTES;
        uint32_t sb = sa + A_STAGE;

        #pragma unroll
        for (int st = 0; st < 2; st++) {
            uint32_t aH[4][4], aL[4][4], bH[4][2], bL[4][2];
            #pragma unroll
            for (int t = 0; t < 4; t++) {
                int row = wm0 + t * 16 + (lane & 15);
                int ch = (st << 1) + (lane >> 4);
                uint32_t addr = sa + row * 128 + ((ch ^ (row & 7)) << 4);
                ldsm4(aH[t][0], aH[t][1], aH[t][2], aH[t][3], addr);
            }
            #pragma unroll
            for (int pr = 0; pr < 2; pr++) {
                int g = lane >> 3, j2 = lane & 7;
                int row = st * 16 + ((g & 1) << 3) + j2;
                int ch = (wn0 >> 3) + (pr << 1) + (g >> 1);
                uint32_t addr = sb + row * 512 + ((ch ^ (row & 7)) << 4);
                ldsm4t(bH[2*pr][0], bH[2*pr][1], bH[2*pr+1][0], bH[2*pr+1][1], addr);
            }
            #pragma unroll
            for (int i = 0; i < 4; i++)
                #pragma unroll
                for (int j = 0; j < 4; j++)
                    mma16816(acc[i][j], aH[i], bH[j]);      // hi*hi
            #pragma unroll
            for (int pr = 0; pr < 2; pr++) {
                int g = lane >> 3, j2 = lane & 7;
                int row = st * 16 + ((g & 1) << 3) + j2;
                int ch = 16 + (wn0 >> 3) + (pr << 1) + (g >> 1);
                uint32_t addr = sb + row * 512 + ((ch ^ (row & 7)) << 4);
                ldsm4t(bL[2*pr][0], bL[2*pr][1], bL[2*pr+1][0], bL[2*pr+1][1], addr);
            }
            #pragma unroll
            for (int i = 0; i < 4; i++)
                #pragma unroll
                for (int j = 0; j < 4; j++)
                    mma16816(acc[i][j], aH[i], bL[j]);      // hi*lo
            #pragma unroll
            for (int t = 0; t < 4; t++) {
                int row = wm0 + t * 16 + (lane & 15);
                int ch = 4 + (st << 1) + (lane >> 4);
                uint32_t addr = sa + row * 128 + ((ch ^ (row & 7)) << 4);
                ldsm4(aL[t][0], aL[t][1], aL[t][2], aL[t][3], addr);
            }
            #pragma unroll
            for (int i = 0; i < 4; i++)
                #pragma unroll
                for (int j = 0; j < 4; j++)
                    mma16816(acc[i][j], aL[i], bH[j]);      // lo*hi
        }

        if (ks + 2 < 32) load_stage(ks + 2);
        asm volatile("cp.async.commit_group;" ::: "memory");
    }

    #pragma unroll
    for (int i = 0; i < 4; i++) {
        #pragma unroll
        for (int j = 0; j < 4; j++) {
            int row = m0 + wm0 + i * 16 + (lane >> 2);
            int col = n0 + wn0 + j * 8 + ((lane & 3) << 1);
            #pragma unroll
            for (int half = 0; half < 2; half++) {
                int rr = row + half * 8;
                float v0 = acc[i][j][half * 2 + 0];
                float v1 = acc[i][j][half * 2 + 1];
                size_t gi = (size_t)rr * 1024 + col;
                if (ADD_O) {
                    bf162 oh = *(const bf162*)(Oh + gi);
                    bf162 ol = *(const bf162*)(Ol + gi);
                    v0 += __bfloat162float(oh.x) + __bfloat162float(ol.x);
                    v1 += __bfloat162float(oh.y) + __bfloat162float(ol.y);
                }
                bf16 h0 = __float2bfloat16(v0);
                bf16 l0 = __float2bfloat16(v0 - __bfloat162float(h0));
                bf16 h1 = __float2bfloat16(v1);
                bf16 l1 = __float2bfloat16(v1 - __bfloat162float(h1));
                bf162 hh; hh.x = h0; hh.y = h1;
                bf162 ll; ll.x = l0; ll.y = l1;
                *(bf162*)(Ch + gi) = hh;
                *(bf162*)(Cl + gi) = ll;
            }
        }
    }
}

// ---------------- Gram: G[b,l,t] = sum_d C[b,l,d]*B[b,t,d] ----------------
__global__ void gram_kernel(const float* __restrict__ Bm, const float* __restrict__ Cm) {
    int b = blockIdx.z;
    __shared__ float Cs[16][65];
    __shared__ float Bs[16][65];
    int tid = threadIdx.y * 16 + threadIdx.x;
    for (int i = tid; i < 16 * 64; i += 256) {
        int r = i >> 6, d = i & 63;
        Cs[r][d] = Cm[((size_t)b * LN + blockIdx.y * 16 + r) * DS + d];
        Bs[r][d] = Bm[((size_t)b * LN + blockIdx.x * 16 + r) * DS + d];
    }
    __syncthreads();
    float acc = 0.f;
    #pragma unroll
    for (int d = 0; d < DS; d++) acc += Cs[threadIdx.y][d] * Bs[threadIdx.x][d];
    int row = blockIdx.y * 16 + threadIdx.y;
    int col = blockIdx.x * 16 + threadIdx.x;
    g_G[((size_t)b * LN + row) * LN + col] = acc;
}

// ---------------- final: block = 8 l-rows x one (h,b); x staged in SMEM ----------------
// y[b,h,l,e] = sum_t W[l,t]*x[t,e] + D[h]*x[l,e],  W[l,t] = (Lh+Ll)[l,t]*ds[t]*G[l,t]
__global__ void __launch_bounds__(128)
final_kernel(const float* __restrict__ x, const float* __restrict__ D,
             const bf16* __restrict__ Fh, const bf16* __restrict__ Fl,
             float* __restrict__ out) {
    const int lb = blockIdx.x * 8;       // 8 l-rows per block
    const int h = blockIdx.y, b = blockIdx.z;
    const int tid = threadIdx.x;
    const size_t bh = (size_t)(b * NH + h);

    __shared__ float xs[128][HD];        // x chunk [t][e]
    __shared__ float ws[8][128];         // weights [l_loc][t]

    const int l_loc = tid >> 4;          // 0..7
    const int e     = tid & 15;          // 0..15
    const int wl    = tid >> 4;          // weight row (same partition)
    const int wt0   = (tid & 15) << 3;   // 8 t per thread in phase 1

    const float* ds = g_dtself + (bh << 10);
    float acc = 0.f;

    for (int ch = 0; ch < 8; ch++) {
        int t0 = ch << 7;
        // stage x[t0..t0+127][h*16..h*16+15]  (each thread: one t-row, 16 floats)
        {
            const float4* xp = (const float4*)(x + (((size_t)(b << 10) + t0 + tid) << 7) + h * HD);
            float4 v0 = xp[0], v1 = xp[1], v2 = xp[2], v3 = xp[3];
            xs[tid][0] = v0.x; xs[tid][1] = v0.y; xs[tid][2] = v0.z; xs[tid][3] = v0.w;
            xs[tid][4] = v1.x; xs[tid][5] = v1.y; xs[tid][6] = v1.z; xs[tid][7] = v1.w;
            xs[tid][8] = v2.x; xs[tid][9] = v2.y; xs[tid][10] = v2.z; xs[tid][11] = v2.w;
            xs[tid][12] = v3.x; xs[tid][13] = v3.y; xs[tid][14] = v3.z; xs[tid][15] = v3.w;
        }
        // stage weights for 8 l-rows
        {
            int l = lb + wl;
            const bf16* Lh = Fh + ((bh << 10) + l) * 1024 + t0 + wt0;
            const bf16* Ll = Fl + ((bh << 10) + l) * 1024 + t0 + wt0;
            const float* Gp = g_G + (((size_t)b << 10) + l) * 1024 + t0 + wt0;
            #pragma unroll
            for (int q = 0; q < 8; q++) {
                float Lv = __bfloat162float(Lh[q]) + __bfloat162float(Ll[q]);
                ws[wl][wt0 + q] = Lv * ds[t0 + wt0 + q] * Gp[q];
            }
        }
        __syncthreads();
        #pragma unroll 8
        for (int t = 0; t < 128; t++)
            acc += ws[l_loc][t] * xs[t][e];
        __syncthreads();
    }

    int l = lb + l_loc;
    size_t node = ((size_t)b << 10) + l;
    float xv = x[(node << 7) + h * HD + e];
    out[(node << 7) + e * NH + h] = acc + D[h] * xv;
}

// ---------------- launch ----------------
extern "C" void kernel_launch(void* const* d_in, const int* in_sizes, int n_in,
                              void* d_out, int out_size) {
    const float* x       = (const float*)d_in[0];
    const float* Bm      = (const float*)d_in[1];
    const float* Cm      = (const float*)d_in[2];
    const float* dt      = (const float*)d_in[3];
    const float* dt_bias = (const float*)d_in[4];
    const float* Dv      = (const float*)d_in[5];
    const int*   edges   = (const int*)d_in[6];
    float* out = (float*)d_out;

    float* pT;
    cudaGetSymbolAddress((void**)&pT, g_T);
    bf16 *Lh,*Ll,*Sh,*Sl,*Oh,*Ol,*Ph,*Pl;
    cudaGetSymbolAddress((void**)&Lh, g_Lh); cudaGetSymbolAddress((void**)&Ll, g_Ll);
    cudaGetSymbolAddress((void**)&Sh, g_Sh); cudaGetSymbolAddress((void**)&Sl, g_Sl);
    cudaGetSymbolAddress((void**)&Oh, g_Oh); cudaGetSymbolAddress((void**)&Ol, g_Ol);
    cudaGetSymbolAddress((void**)&Ph, g_Ph); cudaGetSymbolAddress((void**)&Pl, g_Pl);

    cudaFuncSetAttribute(hgemm_kernel<false>,
                         cudaFuncAttributeMaxDynamicSharedMemorySize, SMEM_REQ);
    cudaFuncSetAttribute(hgemm_kernel<true>,
                         cudaFuncAttributeMaxDynamicSharedMemorySize, SMEM_REQ);

    coef_kernel<<<(NNODE + 255) / 256, 256>>>(dt, dt_bias);
    zero_kernel<<<(int)(BH * MSZ / 4 / 256), 256>>>((float4*)pT);
    scatter_kernel<<<NEDGE / 128, 128>>>(edges, edges + NEDGE);
    build_kernel<<<(int)(BH * MSZ / 4 / 256), 256>>>();

    dim3 gg(8, 8, BH);
    for (int it = 0; it < 5; it++) {
        // S = L @ L
        hgemm_kernel<false><<<gg, 256, SMEM_REQ>>>(Lh, Ll, Lh, Ll, Sh, Sl, Lh, Ll);
        // P = O @ S + O
        hgemm_kernel<true><<<gg, 256, SMEM_REQ>>>(Oh, Ol, Sh, Sl, Ph, Pl, Oh, Ol);
        bf16* t;
        t = Lh; Lh = Sh; Sh = t;  t = Ll; Ll = Sl; Sl = t;
        t = Oh; Oh = Ph; Ph = t;  t = Ol; Ol = Pl; Pl = t;
    }

    gram_kernel<<<dim3(64, 64, NG), dim3(16, 16)>>>(Bm, Cm);
    final_kernel<<<dim3(LN / 8, NH, NG), 128>>>(x, Dv, Oh, Ol, out);
}

// round 15
// speedup vs baseline: 1.1193x; 1.0381x over previous
#include <cuda_runtime.h>
#include <cuda_bf16.h>
#include <math.h>
#include <stdint.h>

#define NG 8
#define LN 1024
#define NH 8
#define HD 16
#define DS 64
#define NNODE (NG*LN)
#define NEDGE 131072
#define BH (NG*NH)
#define MSZ (1024ULL*1024ULL)

typedef __nv_bfloat16 bf16;
typedef __nv_bfloat162 bf162;

// ---------------- scratch (__device__ globals, allocation-free) ----------------
__device__ float g_T[BH*MSZ];
__device__ float g_G[NG*MSZ];
__device__ float g_s0[NH*NNODE], g_s1[NH*NNODE];
__device__ float g_denom[BH*LN], g_dtself[BH*LN];
__device__ bf16 g_Lh[BH*MSZ], g_Ll[BH*MSZ];
__device__ bf16 g_Sh[BH*MSZ], g_Sl[BH*MSZ];
__device__ bf16 g_Oh[BH*MSZ], g_Ol[BH*MSZ];
__device__ bf16 g_Ph[BH*MSZ], g_Pl[BH*MSZ];

// ---------------- PTX helpers (plain-sm_103-legal) ----------------
__device__ __forceinline__ uint32_t smem_u32(const void* p) {
    uint32_t a;
    asm("{ .reg .u64 t; cvta.to.shared.u64 t, %1; cvt.u32.u64 %0, t; }" : "=r"(a) : "l"(p));
    return a;
}
__device__ __forceinline__ void cp16(uint32_t dst, const void* src) {
    asm volatile("cp.async.cg.shared.global [%0], [%1], 16;" :: "r"(dst), "l"(src));
}
__device__ __forceinline__ void ldsm4(uint32_t& r0, uint32_t& r1, uint32_t& r2, uint32_t& r3,
                                      uint32_t addr) {
    asm volatile("ldmatrix.sync.aligned.m8n8.x4.shared.b16 {%0,%1,%2,%3}, [%4];"
                 : "=r"(r0), "=r"(r1), "=r"(r2), "=r"(r3) : "r"(addr));
}
__device__ __forceinline__ void ldsm4t(uint32_t& r0, uint32_t& r1, uint32_t& r2, uint32_t& r3,
                                       uint32_t addr) {
    asm volatile("ldmatrix.sync.aligned.m8n8.x4.trans.shared.b16 {%0,%1,%2,%3}, [%4];"
                 : "=r"(r0), "=r"(r1), "=r"(r2), "=r"(r3) : "r"(addr));
}
__device__ __forceinline__ void mma16816(float* c, const uint32_t* a, const uint32_t* b) {
    asm volatile(
        "mma.sync.aligned.m16n8k16.row.col.f32.bf16.bf16.f32 "
        "{%0,%1,%2,%3}, {%4,%5,%6,%7}, {%8,%9}, {%0,%1,%2,%3};"
        : "+f"(c[0]), "+f"(c[1]), "+f"(c[2]), "+f"(c[3])
        : "r"(a[0]), "r"(a[1]), "r"(a[2]), "r"(a[3]), "r"(b[0]), "r"(b[1]));
}

// ---------------- prep ----------------
__device__ __forceinline__ float softplus_f(float z) {
    return (z > 20.f) ? z : log1pf(expf(z));
}

__global__ void coef_kernel(const float* __restrict__ dt, const float* __restrict__ dt_bias) {
    int n = blockIdx.x * 256 + threadIdx.x;
    if (n >= NNODE) return;
    int b = n >> 10, l = n & 1023;
    #pragma unroll
    for (int h = 0; h < NH; h++) {
        float bias = dt_bias[h];
        const float* p = dt + (size_t)n * (NH * 4) + h * 4;
        float a0 = -softplus_f(p[0] + bias);
        float a1 = -softplus_f(p[1] + bias);
        float a2 = -softplus_f(p[2] + bias);
        g_s0[h * NNODE + n] = expf(0.5f * a0);
        g_s1[h * NNODE + n] = expf(0.5f * a1);
        g_denom[(b * NH + h) * LN + l] = expf(a2) + 0.1f;
        g_dtself[(b * NH + h) * LN + l] = p[3];
    }
}

__global__ void zero_kernel(float4* __restrict__ p) {
    size_t i = (size_t)blockIdx.x * 256 + threadIdx.x;
    p[i] = make_float4(0.f, 0.f, 0.f, 0.f);
}

__global__ void scatter_kernel(const int* __restrict__ src, const int* __restrict__ dst) {
    int e = blockIdx.x * 128 + threadIdx.x;
    if (e >= NEDGE) return;
    int s = src[e], d = dst[e];
    int b = s >> 10, sl = s & 1023, dl = d & 1023;
    #pragma unroll
    for (int h = 0; h < NH; h++) {
        float attr = g_s0[h * NNODE + s] * g_s1[h * NNODE + d];
        size_t base = ((size_t)(b * NH + h) * LN + dl) * LN + sl;  // transposed layout
        atomicAdd(&g_T[base], attr);
        atomicAdd(&g_denom[(b * NH + h) * LN + sl], attr);
    }
}

// M[bh,i,j] = g_T[bh,i,j] / denom[bh,j];  L = M (hi/lo);  O = I + M (hi/lo)
__global__ void build_kernel() {
    size_t q = (size_t)blockIdx.x * 256 + threadIdx.x;
    size_t idx = q << 2;
    int j0 = (int)(idx & 1023);
    size_t r = idx >> 10;
    int bh = (int)(r >> 10);
    int i  = (int)(r & 1023);
    float4 v4 = *(const float4*)(g_T + idx);
    float4 d4 = *(const float4*)(g_denom + bh * LN + j0);
    float v[4] = { v4.x / d4.x, v4.y / d4.y, v4.z / d4.z, v4.w / d4.w };
    bf16 lh[4], ll[4], oh[4], ol[4];
    #pragma unroll
    for (int q2 = 0; q2 < 4; q2++) {
        float x = v[q2];
        bf16 h = __float2bfloat16(x);
        lh[q2] = h;
        ll[q2] = __float2bfloat16(x - __bfloat162float(h));
        float xo = x + ((i == j0 + q2) ? 1.f : 0.f);
        bf16 ho = __float2bfloat16(xo);
        oh[q2] = ho;
        ol[q2] = __float2bfloat16(xo - __bfloat162float(ho));
    }
    *(uint2*)(g_Lh + idx) = *(uint2*)lh;
    *(uint2*)(g_Ll + idx) = *(uint2*)ll;
    *(uint2*)(g_Oh + idx) = *(uint2*)oh;
    *(uint2*)(g_Ol + idx) = *(uint2*)ol;
}

// ---------------- fused bf16-split HMMA GEMM ----------------
// grid.z in [0, nSq): squaring  Snext = Scur @ Scur          (no add)
// grid.z in [nSq, ..): multiply Onext = Ocur + Ocur @ Scur   (add Ocur)
// Block 128x128, 8 warps, warp tile 64x32, K-stage 32, 3-stage cp.async, 2 CTAs/SM.
#define STAGES 3
#define A_STAGE 16384
#define B_STAGE 16384
#define STAGE_BYTES (A_STAGE + B_STAGE)
#define SMEM_REQ (STAGES * STAGE_BYTES)

__global__ void __launch_bounds__(256, 2)
hgemm_fused(const bf16* __restrict__ Sch, const bf16* __restrict__ Scl,
            bf16* __restrict__ Snh, bf16* __restrict__ Snl,
            const bf16* __restrict__ Och, const bf16* __restrict__ Ocl,
            bf16* __restrict__ Onh, bf16* __restrict__ Onl,
            int nSq)
{
    extern __shared__ char smraw[];
    const uint32_t sbase = smem_u32(smraw);

    const int tid = threadIdx.x;
    const int lane = tid & 31;
    const int warp = tid >> 5;
    const int wm0 = (warp & 1) * 64;
    const int wn0 = (warp >> 1) * 32;
    const int m0 = blockIdx.y * 128;
    const int n0 = blockIdx.x * 128;

    const bool isMul = (int)blockIdx.z >= nSq;
    const int batch = isMul ? (int)blockIdx.z - nSq : (int)blockIdx.z;
    const size_t zoff = (size_t)batch * MSZ;

    const bf16* Ah = (isMul ? Och : Sch) + zoff;
    const bf16* Al = (isMul ? Ocl : Scl) + zoff;
    const bf16* Bh = Sch + zoff;
    const bf16* Bl = Scl + zoff;
    bf16* Ch = (isMul ? Onh : Snh) + zoff;
    bf16* Cl = (isMul ? Onl : Snl) + zoff;
    const bf16* Oh = Och + zoff;
    const bf16* Ol = Ocl + zoff;

    auto load_stage = [&](int ks) {
        int s = ks % STAGES;
        int k0 = ks << 5;
        uint32_t sa = sbase + s * STAGE_BYTES;
        uint32_t sb = sa + A_STAGE;
        #pragma unroll
        for (int i = 0; i < 4; i++) {
            int idx = tid + (i << 8);
            int r = idx >> 3, c = idx & 7;
            uint32_t dst = sa + r * 128 + ((c ^ (r & 7)) << 4);
            const bf16* src = ((c & 4) ? Al : Ah) + (size_t)(m0 + r) * 1024 + k0 + ((c & 3) << 3);
            cp16(dst, src);
        }
        #pragma unroll
        for (int i = 0; i < 4; i++) {
            int idx = tid + (i << 8);
            int r = idx >> 5, c = idx & 31;
            uint32_t dst = sb + r * 512 + ((c ^ (r & 7)) << 4);
            const bf16* src = ((c & 16) ? Bl : Bh) + (size_t)(k0 + r) * 1024 + n0 + ((c & 15) << 3);
            cp16(dst, src);
        }
    };

    float acc[4][4][4];
    #pragma unroll
    for (int i = 0; i < 4; i++)
        #pragma unroll
        for (int j = 0; j < 4; j++)
            #pragma unroll
            for (int q = 0; q < 4; q++) acc[i][j][q] = 0.f;

    load_stage(0);
    asm volatile("cp.async.commit_group;" ::: "memory");
    load_stage(1);
    asm volatile("cp.async.commit_group;" ::: "memory");

    for (int ks = 0; ks < 32; ks++) {
        asm volatile("cp.async.wait_group 1;" ::: "memory");
        __syncthreads();
        int s = ks % STAGES;
        uint32_t sa = sbase + s * STAGE_BYTES;
        uint32_t sb = sa + A_STAGE;

        #pragma unroll
        for (int st = 0; st < 2; st++) {
            uint32_t aH[4][4], aL[4][4], bH[4][2], bL[4][2];
            #pragma unroll
            for (int t = 0; t < 4; t++) {
                int row = wm0 + t * 16 + (lane & 15);
                int ch = (st << 1) + (lane >> 4);
                uint32_t addr = sa + row * 128 + ((ch ^ (row & 7)) << 4);
                ldsm4(aH[t][0], aH[t][1], aH[t][2], aH[t][3], addr);
            }
            #pragma unroll
            for (int pr = 0; pr < 2; pr++) {
                int g = lane >> 3, j2 = lane & 7;
                int row = st * 16 + ((g & 1) << 3) + j2;
                int ch = (wn0 >> 3) + (pr << 1) + (g >> 1);
                uint32_t addr = sb + row * 512 + ((ch ^ (row & 7)) << 4);
                ldsm4t(bH[2*pr][0], bH[2*pr][1], bH[2*pr+1][0], bH[2*pr+1][1], addr);
            }
            #pragma unroll
            for (int i = 0; i < 4; i++)
                #pragma unroll
                for (int j = 0; j < 4; j++)
                    mma16816(acc[i][j], aH[i], bH[j]);      // hi*hi
            #pragma unroll
            for (int pr = 0; pr < 2; pr++) {
                int g = lane >> 3, j2 = lane & 7;
                int row = st * 16 + ((g & 1) << 3) + j2;
                int ch = 16 + (wn0 >> 3) + (pr << 1) + (g >> 1);
                uint32_t addr = sb + row * 512 + ((ch ^ (row & 7)) << 4);
                ldsm4t(bL[2*pr][0], bL[2*pr][1], bL[2*pr+1][0], bL[2*pr+1][1], addr);
            }
            #pragma unroll
            for (int i = 0; i < 4; i++)
                #pragma unroll
                for (int j = 0; j < 4; j++)
                    mma16816(acc[i][j], aH[i], bL[j]);      // hi*lo
            #pragma unroll
            for (int t = 0; t < 4; t++) {
                int row = wm0 + t * 16 + (lane & 15);
                int ch = 4 + (st << 1) + (lane >> 4);
                uint32_t addr = sa + row * 128 + ((ch ^ (row & 7)) << 4);
                ldsm4(aL[t][0], aL[t][1], aL[t][2], aL[t][3], addr);
            }
            #pragma unroll
            for (int i = 0; i < 4; i++)
                #pragma unroll
                for (int j = 0; j < 4; j++)
                    mma16816(acc[i][j], aL[i], bH[j]);      // lo*hi
        }

        if (ks + 2 < 32) load_stage(ks + 2);
        asm volatile("cp.async.commit_group;" ::: "memory");
    }

    #pragma unroll
    for (int i = 0; i < 4; i++) {
        #pragma unroll
        for (int j = 0; j < 4; j++) {
            int row = m0 + wm0 + i * 16 + (lane >> 2);
            int col = n0 + wn0 + j * 8 + ((lane & 3) << 1);
            #pragma unroll
            for (int half = 0; half < 2; half++) {
                int rr = row + half * 8;
                float v0 = acc[i][j][half * 2 + 0];
                float v1 = acc[i][j][half * 2 + 1];
                size_t gi = (size_t)rr * 1024 + col;
                if (isMul) {
                    bf162 oh = *(const bf162*)(Oh + gi);
                    bf162 ol = *(const bf162*)(Ol + gi);
                    v0 += __bfloat162float(oh.x) + __bfloat162float(ol.x);
                    v1 += __bfloat162float(oh.y) + __bfloat162float(ol.y);
                }
                bf16 h0 = __float2bfloat16(v0);
                bf16 l0 = __float2bfloat16(v0 - __bfloat162float(h0));
                bf16 h1 = __float2bfloat16(v1);
                bf16 l1 = __float2bfloat16(v1 - __bfloat162float(h1));
                bf162 hh; hh.x = h0; hh.y = h1;
                bf162 ll; ll.x = l0; ll.y = l1;
                *(bf162*)(Ch + gi) = hh;
                *(bf162*)(Cl + gi) = ll;
            }
        }
    }
}

// ---------------- Gram: G[b,l,t] = sum_d C[b,l,d]*B[b,t,d] ----------------
__global__ void gram_kernel(const float* __restrict__ Bm, const float* __restrict__ Cm) {
    int b = blockIdx.z;
    __shared__ float Cs[16][65];
    __shared__ float Bs[16][65];
    int tid = threadIdx.y * 16 + threadIdx.x;
    for (int i = tid; i < 16 * 64; i += 256) {
        int r = i >> 6, d = i & 63;
        Cs[r][d] = Cm[((size_t)b * LN + blockIdx.y * 16 + r) * DS + d];
        Bs[r][d] = Bm[((size_t)b * LN + blockIdx.x * 16 + r) * DS + d];
    }
    __syncthreads();
    float acc = 0.f;
    #pragma unroll
    for (int d = 0; d < DS; d++) acc += Cs[threadIdx.y][d] * Bs[threadIdx.x][d];
    int row = blockIdx.y * 16 + threadIdx.y;
    int col = blockIdx.x * 16 + threadIdx.x;
    g_G[((size_t)b * LN + row) * LN + col] = acc;
}

// ---------------- final: block = 8 l-rows x one (h,b); x staged in SMEM ----------------
__global__ void __launch_bounds__(128)
final_kernel(const float* __restrict__ x, const float* __restrict__ D,
             const bf16* __restrict__ Fh, const bf16* __restrict__ Fl,
             float* __restrict__ out) {
    const int lb = blockIdx.x * 8;
    const int h = blockIdx.y, b = blockIdx.z;
    const int tid = threadIdx.x;
    const size_t bh = (size_t)(b * NH + h);

    __shared__ float xs[128][HD];
    __shared__ float ws[8][128];

    const int l_loc = tid >> 4;
    const int e     = tid & 15;
    const int wl    = tid >> 4;
    const int wt0   = (tid & 15) << 3;

    const float* ds = g_dtself + (bh << 10);
    float acc = 0.f;

    for (int ch = 0; ch < 8; ch++) {
        int t0 = ch << 7;
        {
            const float4* xp = (const float4*)(x + (((size_t)(b << 10) + t0 + tid) << 7) + h * HD);
            float4 v0 = xp[0], v1 = xp[1], v2 = xp[2], v3 = xp[3];
            xs[tid][0] = v0.x; xs[tid][1] = v0.y; xs[tid][2] = v0.z; xs[tid][3] = v0.w;
            xs[tid][4] = v1.x; xs[tid][5] = v1.y; xs[tid][6] = v1.z; xs[tid][7] = v1.w;
            xs[tid][8] = v2.x; xs[tid][9] = v2.y; xs[tid][10] = v2.z; xs[tid][11] = v2.w;
            xs[tid][12] = v3.x; xs[tid][13] = v3.y; xs[tid][14] = v3.z; xs[tid][15] = v3.w;
        }
        {
            int l = lb + wl;
            const bf16* Lh = Fh + ((bh << 10) + l) * 1024 + t0 + wt0;
            const bf16* Ll = Fl + ((bh << 10) + l) * 1024 + t0 + wt0;
            const float* Gp = g_G + (((size_t)b << 10) + l) * 1024 + t0 + wt0;
            #pragma unroll
            for (int q = 0; q < 8; q++) {
                float Lv = __bfloat162float(Lh[q]) + __bfloat162float(Ll[q]);
                ws[wl][wt0 + q] = Lv * ds[t0 + wt0 + q] * Gp[q];
            }
        }
        __syncthreads();
        #pragma unroll 8
        for (int t = 0; t < 128; t++)
            acc += ws[l_loc][t] * xs[t][e];
        __syncthreads();
    }

    int l = lb + l_loc;
    size_t node = ((size_t)b << 10) + l;
    float xv = x[(node << 7) + h * HD + e];
    out[(node << 7) + e * NH + h] = acc + D[h] * xv;
}

// ---------------- launch ----------------
extern "C" void kernel_launch(void* const* d_in, const int* in_sizes, int n_in,
                              void* d_out, int out_size) {
    const float* x       = (const float*)d_in[0];
    const float* Bm      = (const float*)d_in[1];
    const float* Cm      = (const float*)d_in[2];
    const float* dt      = (const float*)d_in[3];
    const float* dt_bias = (const float*)d_in[4];
    const float* Dv      = (const float*)d_in[5];
    const int*   edges   = (const int*)d_in[6];
    float* out = (float*)d_out;

    float* pT;
    cudaGetSymbolAddress((void**)&pT, g_T);
    bf16 *Lh,*Ll,*Sh,*Sl,*Oh,*Ol,*Ph,*Pl;
    cudaGetSymbolAddress((void**)&Lh, g_Lh); cudaGetSymbolAddress((void**)&Ll, g_Ll);
    cudaGetSymbolAddress((void**)&Sh, g_Sh); cudaGetSymbolAddress((void**)&Sl, g_Sl);
    cudaGetSymbolAddress((void**)&Oh, g_Oh); cudaGetSymbolAddress((void**)&Ol, g_Ol);
    cudaGetSymbolAddress((void**)&Ph, g_Ph); cudaGetSymbolAddress((void**)&Pl, g_Pl);

    cudaFuncSetAttribute(hgemm_fused,
                         cudaFuncAttributeMaxDynamicSharedMemorySize, SMEM_REQ);

    coef_kernel<<<(NNODE + 255) / 256, 256>>>(dt, dt_bias);
    zero_kernel<<<(int)(BH * MSZ / 4 / 256), 256>>>((float4*)pT);
    scatter_kernel<<<NEDGE / 128, 128>>>(edges, edges + NEDGE);
    build_kernel<<<(int)(BH * MSZ / 4 / 256), 256>>>();

    // Doubling chain via fused (mul_k, sq_{k+1}) launches.
    // State: A in L, O0=I+A in O.
    dim3 g64(8, 8, BH);
    dim3 g128(8, 8, 2 * BH);

    // Launch 1: S = A @ A        (sq only)
    hgemm_fused<<<g64, 256, SMEM_REQ>>>(Lh, Ll, Sh, Sl, Oh, Ol, Ph, Pl, BH);
    // Launch 2: P = O + O@S ; L = S@S   (Scur=S → Snext=L, Ocur=O → Onext=P)
    hgemm_fused<<<g128, 256, SMEM_REQ>>>(Sh, Sl, Lh, Ll, Oh, Ol, Ph, Pl, BH);
    // Launch 3: O = P + P@L ; S = L@L
    hgemm_fused<<<g128, 256, SMEM_REQ>>>(Lh, Ll, Sh, Sl, Ph, Pl, Oh, Ol, BH);
    // Launch 4: P = O + O@S ; L = S@S
    hgemm_fused<<<g128, 256, SMEM_REQ>>>(Sh, Sl, Lh, Ll, Oh, Ol, Ph, Pl, BH);
    // Launch 5: O = P + P@L ; S = L@L
    hgemm_fused<<<g128, 256, SMEM_REQ>>>(Lh, Ll, Sh, Sl, Ph, Pl, Oh, Ol, BH);
    // Launch 6: P = O + O@S      (mul only; final result in P)
    hgemm_fused<<<g64, 256, SMEM_REQ>>>(Sh, Sl, Lh, Ll, Oh, Ol, Ph, Pl, 0);

    gram_kernel<<<dim3(64, 64, NG), dim3(16, 16)>>>(Bm, Cm);
    final_kernel<<<dim3(LN / 8, NH, NG), 128>>>(x, Dv, Ph, Pl, out);
}